// round 12
// baseline (speedup 1.0000x reference)
#include <cuda_runtime.h>
#include <cuda_bf16.h>
#include <math.h>
#include <stdint.h>

// Problem constants
#define B_ 2
#define T_ 2048
#define C_ 2048
#define H_ 16
#define KVH_ 4
#define D_ 128
#define M_ (B_ * T_)          // 4096
#define KVC_ (KVH_ * D_)      // 512
#define SCALE_ 0.08838834764831845f
#define RMS_EPS 1.1920929e-07f

// ---------------------------------------------------------------------------
// Scratch (device globals; no allocation allowed)
// ---------------------------------------------------------------------------
__device__ float g_q[(size_t)M_ * C_];
__device__ float g_k[(size_t)M_ * KVC_];
__device__ float g_v[(size_t)M_ * KVC_];
__device__ float g_y[(size_t)M_ * C_];
__device__ float g_x[(size_t)M_ * C_];
__device__ float g_wq[(size_t)C_ * C_];
__device__ float g_wk[(size_t)C_ * KVC_];
__device__ float g_wv[(size_t)C_ * KVC_];
__device__ float g_wo[(size_t)C_ * C_];

// ---------------------------------------------------------------------------
// helpers
// ---------------------------------------------------------------------------
__device__ __forceinline__ uint32_t smem_u32(const void* p) {
    uint32_t a;
    asm("{ .reg .u64 t; cvta.to.shared.u64 t, %1; cvt.u32.u64 %0, t; }" : "=r"(a) : "l"(p));
    return a;
}

__device__ __forceinline__ float tf32r(float x) {
    unsigned u;
    asm("cvt.rna.tf32.f32 %0, %1;" : "=r"(u) : "f"(x));
    return __uint_as_float(u);
}

__device__ __forceinline__ void cp16(uint32_t s, const void* g) {
    asm volatile("cp.async.cg.shared.global [%0], [%1], 16;" :: "r"(s), "l"(g) : "memory");
}
#define CP_COMMIT() asm volatile("cp.async.commit_group;" ::: "memory")
#define CP_WAIT(n)  asm volatile("cp.async.wait_group %0;" :: "n"(n) : "memory")

__device__ __forceinline__ void mma_tf32(float* c, const float* a, const float* b) {
    const unsigned* A = reinterpret_cast<const unsigned*>(a);
    const unsigned* Bv = reinterpret_cast<const unsigned*>(b);
    asm volatile(
        "mma.sync.aligned.m16n8k8.row.col.f32.tf32.tf32.f32 "
        "{%0,%1,%2,%3}, {%4,%5,%6,%7}, {%8,%9}, {%0,%1,%2,%3};\n"
        : "+f"(c[0]), "+f"(c[1]), "+f"(c[2]), "+f"(c[3])
        : "r"(A[0]), "r"(A[1]), "r"(A[2]), "r"(A[3]), "r"(Bv[0]), "r"(Bv[1]));
}

// ---------------------------------------------------------------------------
// tf32 pre-round kernel
// ---------------------------------------------------------------------------
__global__ __launch_bounds__(256) void tf32_round_kernel(
    const float4* __restrict__ src, float4* __restrict__ dst, int n4)
{
    int i = blockIdx.x * 256 + threadIdx.x;
    if (i < n4) {
        float4 v = src[i];
        dst[i] = make_float4(tf32r(v.x), tf32r(v.y), tf32r(v.z), tf32r(v.w));
    }
}

// ---------------------------------------------------------------------------
// cp.async 3-stage pipelined tf32 GEMM mainloop (unchanged from R11).
// Tile 128x128, K-step 32, 256 threads (8 warps 2x4), warp tile 64x32.
// ---------------------------------------------------------------------------
#define A_ST 36
#define B_ST 136
#define ABUF (128 * A_ST)
#define BBUF (32 * B_ST)
#define STAGES 3
#define GEMM_SM_FLOATS (STAGES * (ABUF + BBUF))   // 107520 B
#define STAGE_ST 132

__device__ __forceinline__ void gemm_main(
    const float* __restrict__ Ab, const float* __restrict__ Bb,
    int Nb, int K, float* sm, float acc[4][4][4])
{
    float* As = sm;
    float* Bs = sm + STAGES * ABUF;
    const uint32_t sA = smem_u32(As);
    const uint32_t sB = smem_u32(Bs);

    const int tid = threadIdx.x;
    const int lane = tid & 31;
    const int wid = tid >> 5;
    const int t4 = lane >> 2;
    const int tm4 = lane & 3;
    const int wy = wid & 1;
    const int wx = wid >> 1;

    #pragma unroll
    for (int i = 0; i < 4; i++)
        #pragma unroll
        for (int j = 0; j < 4; j++)
            #pragma unroll
            for (int r = 0; r < 4; r++) acc[i][j][r] = 0.f;

    const int NT = K >> 5;

    auto load_stage = [&](int t, int slot) {
        const float* An = Ab + t * 32;
        const float* Bn = Bb + (size_t)(t * 32) * Nb;
        #pragma unroll
        for (int i = 0; i < 4; i++) {
            int idx = tid + i * 256;
            int r = idx >> 3, cg = (idx & 7) << 2;
            cp16(sA + (uint32_t)(slot * ABUF + r * A_ST + cg) * 4,
                 An + (size_t)r * K + cg);
        }
        #pragma unroll
        for (int i = 0; i < 4; i++) {
            int idx = tid + i * 256;
            int r = idx >> 5, c = (idx & 31) << 2;
            cp16(sB + (uint32_t)(slot * BBUF + r * B_ST + c) * 4,
                 Bn + (size_t)r * Nb + c);
        }
    };

    #pragma unroll
    for (int s = 0; s < STAGES - 1; s++) {
        if (s < NT) load_stage(s, s);
        CP_COMMIT();
    }

    int slot = 0;
    for (int t = 0; t < NT; t++) {
        CP_WAIT(STAGES - 2);
        __syncthreads();

        int u = t + STAGES - 1;
        int uslot = slot + STAGES - 1;
        if (uslot >= STAGES) uslot -= STAGES;
        if (u < NT) load_stage(u, uslot);
        CP_COMMIT();

        float* Asb = As + slot * ABUF;
        float* Bsb = Bs + slot * BBUF;
        #pragma unroll
        for (int ks = 0; ks < 32; ks += 8) {
            float afr[4][4], bfr[4][2];
            #pragma unroll
            for (int mi = 0; mi < 4; mi++) {
                int rb = wy * 64 + mi * 16;
                afr[mi][0] = Asb[(rb + t4) * A_ST + ks + tm4];
                afr[mi][1] = Asb[(rb + 8 + t4) * A_ST + ks + tm4];
                afr[mi][2] = Asb[(rb + t4) * A_ST + ks + tm4 + 4];
                afr[mi][3] = Asb[(rb + 8 + t4) * A_ST + ks + tm4 + 4];
            }
            #pragma unroll
            for (int ni = 0; ni < 4; ni++) {
                int cb = wx * 32 + ni * 8;
                bfr[ni][0] = Bsb[(ks + tm4) * B_ST + cb + t4];
                bfr[ni][1] = Bsb[(ks + tm4 + 4) * B_ST + cb + t4];
            }
            #pragma unroll
            for (int mi = 0; mi < 4; mi++)
                #pragma unroll
                for (int ni = 0; ni < 4; ni++)
                    mma_tf32(acc[mi][ni], afr[mi], bfr[ni]);
        }
        if (++slot == STAGES) slot = 0;
    }
}

// Plain epilogue
template <bool ROUND>
__device__ __forceinline__ void epi_plain(float acc[4][4][4], float* out, int Nout)
{
    const int tid = threadIdx.x;
    const int lane = tid & 31;
    const int wid = tid >> 5;
    const int t4 = lane >> 2;
    const int tm4 = lane & 3;
    const int wy = wid & 1;
    const int wx = wid >> 1;
    #pragma unroll
    for (int mi = 0; mi < 4; mi++) {
        int row = wy * 64 + mi * 16 + t4;
        #pragma unroll
        for (int ni = 0; ni < 4; ni++) {
            int col = wx * 32 + ni * 8 + tm4 * 2;
            float a0 = acc[mi][ni][0], a1 = acc[mi][ni][1];
            float a2 = acc[mi][ni][2], a3 = acc[mi][ni][3];
            if (ROUND) { a0 = tf32r(a0); a1 = tf32r(a1); a2 = tf32r(a2); a3 = tf32r(a3); }
            *(float2*)(out + (size_t)row * Nout + col) = make_float2(a0, a1);
            *(float2*)(out + (size_t)(row + 8) * Nout + col) = make_float2(a2, a3);
        }
    }
}

// RoPE + RMSNorm epilogue (stores tf32-rounded)
__device__ __forceinline__ void epi_rope(
    float acc[4][4][4], float* sm,
    const float* __restrict__ cs, const float* __restrict__ sn,
    float* out, int Nout, int m0)
{
    float* stage = sm;
    const int tid = threadIdx.x;
    const int lane = tid & 31;
    const int wid = tid >> 5;
    const int t4 = lane >> 2;
    const int tm4 = lane & 3;
    const int wy = wid & 1;
    const int wx = wid >> 1;

    __syncthreads();
    #pragma unroll
    for (int mi = 0; mi < 4; mi++) {
        int row = wy * 64 + mi * 16 + t4;
        #pragma unroll
        for (int ni = 0; ni < 4; ni++) {
            int col = wx * 32 + ni * 8 + tm4 * 2;
            *(float2*)(&stage[row * STAGE_ST + col]) = make_float2(acc[mi][ni][0], acc[mi][ni][1]);
            *(float2*)(&stage[(row + 8) * STAGE_ST + col]) = make_float2(acc[mi][ni][2], acc[mi][ni][3]);
        }
    }
    __syncthreads();

    {
        const int r = tid >> 1;
        const int hf = tid & 1;
        const int tpos = (m0 + r) & (T_ - 1);
        const float* cr = cs + tpos * 64;
        const float* sr = sn + tpos * 64;
        float* row = &stage[r * STAGE_ST];

        float ss = 0.f;
        #pragma unroll 8
        for (int j = 0; j < 64; j++) {
            float x1 = row[j], x2 = row[j + 64];
            float c = cr[j], s = sr[j];
            float val = hf ? (x2 * c - x1 * s) : (x1 * c + x2 * s);
            ss += val * val;
        }
        ss += __shfl_xor_sync(0xffffffffu, ss, 1);
        float inv = rsqrtf(ss * (1.f / 128.f) + RMS_EPS);

        #pragma unroll 8
        for (int j = 0; j < 64; j++) {
            float x1 = row[j], x2 = row[j + 64];
            float c = cr[j], s = sr[j];
            float val = hf ? (x2 * c - x1 * s) : (x1 * c + x2 * s);
            row[hf * 64 + j] = tf32r(val * inv);
        }
    }
    __syncthreads();

    {
        const int c4 = lane * 4;
        const int rb = tid >> 5;
        #pragma unroll
        for (int p = 0; p < 16; p++) {
            int row = p * 8 + rb;
            float4 v = *(const float4*)(&stage[row * STAGE_ST + c4]);
            *(float4*)(out + (size_t)row * Nout + c4) = v;
        }
    }
}

// ---------------------------------------------------------------------------
// Fused QKV projection + RoPE + RMSNorm. grid (24, 32), 256 threads, 2 CTA/SM.
// ---------------------------------------------------------------------------
__global__ __launch_bounds__(256, 2) void gemm_qkv(
    const float* __restrict__ x,
    const float* __restrict__ Wq, const float* __restrict__ Wk, const float* __restrict__ Wv,
    const float* __restrict__ cs, const float* __restrict__ sn,
    float* __restrict__ q, float* __restrict__ k, float* __restrict__ v)
{
    extern __shared__ float sm[];
    const int bx = blockIdx.x;
    const int m0 = blockIdx.y * 128;

    const float* Bw;
    float* outp;
    int Nb, colt;
    bool dorope;
    if (bx < 16)      { Bw = Wq; outp = q; Nb = C_;   colt = bx * 128;        dorope = true; }
    else if (bx < 20) { Bw = Wk; outp = k; Nb = KVC_; colt = (bx - 16) * 128; dorope = true; }
    else              { Bw = Wv; outp = v; Nb = KVC_; colt = (bx - 20) * 128; dorope = false; }

    float acc[4][4][4];
    gemm_main(x + (size_t)m0 * C_, Bw + colt, Nb, C_, sm, acc);

    float* out_tile = outp + (size_t)m0 * Nb + colt;
    if (dorope) epi_rope(acc, sm, cs, sn, out_tile, Nb, m0);
    else        epi_plain<true>(acc, out_tile, Nb);
}

// ---------------------------------------------------------------------------
// Output projection: out = y @ Wo. grid (16, 32), 256 threads, 2 CTA/SM.
// ---------------------------------------------------------------------------
__global__ __launch_bounds__(256, 2) void gemm_out(
    const float* __restrict__ y, const float* __restrict__ Wo, float* __restrict__ out)
{
    extern __shared__ float sm[];
    const int m0 = blockIdx.y * 128;
    const int colt = blockIdx.x * 128;
    float acc[4][4][4];
    gemm_main(y + (size_t)m0 * C_, Wo + colt, C_, C_, sm, acc);
    epi_plain<false>(acc, out + (size_t)m0 * C_ + colt, C_);
}

// ---------------------------------------------------------------------------
// Flash attention (causal, GQA rep=4), tf32 mma.
// Br=128, Bc=64, 512 threads (16 warps 4x4).
//   S warp tile 32x16 (per-warp shape = R9), PV warp tile 32x32.
// K double-buffered, V single-buffered; cp.async group FIFO:
//   K(kt+1) issued at loop top (covered by S-phase),
//   V(kt+1) issued after PV (covered by next S-phase).
// ---------------------------------------------------------------------------
#define FA_BR 128
#define FA_BC 64
#define Q_ST 132
#define K_ST 132
#define V_ST 136
#define S_ST 68

#define SM_Q   0
#define SM_K   (FA_BR * Q_ST)                    // 16896
#define SM_V   (SM_K + 2 * FA_BC * K_ST)         // 33792
#define SM_S   (SM_V + FA_BC * V_ST)             // 42496
#define SM_M   (SM_S + FA_BR * S_ST)             // 51200
#define SM_L   (SM_M + FA_BR)
#define SM_A   (SM_L + FA_BR)
#define FA_SMEM_FLOATS (SM_A + FA_BR)            // 51584 floats = 206336 B

__global__ __launch_bounds__(512, 1) void flash_attn_tf32(
    const float* __restrict__ q, const float* __restrict__ k,
    const float* __restrict__ v, float* __restrict__ y)
{
    extern __shared__ float sm[];
    float* Qs = sm + SM_Q;
    float* Ks = sm + SM_K;
    float* Vs = sm + SM_V;
    float* Ss = sm + SM_S;
    float* m_s = sm + SM_M;
    float* l_s = sm + SM_L;
    float* a_s = sm + SM_A;
    const uint32_t sbase = smem_u32(sm);

    const int tid = threadIdx.x;
    const int lane = tid & 31;
    const int wid = tid >> 5;
    const int t4 = lane >> 2;
    const int tm4 = lane & 3;
    const int wy = wid & 3;      // 4 warp-rows x 32 rows
    const int wx = wid >> 2;     // 4 warp-cols

    const int bh = blockIdx.y;
    const int b = bh >> 4;
    const int h = bh & 15;
    const int kvh = h >> 2;
    const int qt = gridDim.x - 1 - blockIdx.x;   // reversed: long CTAs first
    const int q0 = qt * FA_BR;
    const int L = 2 * qt + 1;                    // last k-tile index

    const float* qbase = q + (size_t)b * T_ * C_ + h * D_;
    const float* kbase = k + (size_t)b * T_ * KVC_ + kvh * D_;
    const float* vbase = v + (size_t)b * T_ * KVC_ + kvh * D_;

    auto issue_k = [&](int kt, int slot) {
        const float* kb = kbase + (size_t)(kt * FA_BC) * KVC_;
        #pragma unroll
        for (int i = 0; i < 4; i++) {
            int idx = tid + i * 512;
            int r = idx >> 5;
            int c = (idx & 31) << 2;
            cp16(sbase + (uint32_t)(SM_K + slot * FA_BC * K_ST + r * K_ST + c) * 4,
                 kb + (size_t)r * KVC_ + c);
        }
    };
    auto issue_v = [&](int kt) {
        const float* vb = vbase + (size_t)(kt * FA_BC) * KVC_;
        #pragma unroll
        for (int i = 0; i < 4; i++) {
            int idx = tid + i * 512;
            int r = idx >> 5;
            int c = (idx & 31) << 2;
            cp16(sbase + (uint32_t)(SM_V + r * V_ST + c) * 4,
                 vb + (size_t)r * KVC_ + c);
        }
    };

    // Prologue: {Q, K0} group, then {V0} group
    #pragma unroll
    for (int i = 0; i < 8; i++) {
        int idx = tid + i * 512;
        int r = idx >> 5;
        int c = (idx & 31) << 2;
        cp16(sbase + (uint32_t)(SM_Q + r * Q_ST + c) * 4,
             qbase + (size_t)(q0 + r) * C_ + c);
    }
    issue_k(0, 0);
    CP_COMMIT();
    issue_v(0);
    CP_COMMIT();

    if (tid < FA_BR) { m_s[tid] = -INFINITY; l_s[tid] = 0.f; }

    float o[2][4][4];
    #pragma unroll
    for (int i = 0; i < 2; i++)
        #pragma unroll
        for (int j = 0; j < 4; j++)
            #pragma unroll
            for (int r = 0; r < 4; r++) o[i][j][r] = 0.f;

    for (int kt = 0; kt <= L; kt++) {
        const int slot = kt & 1;
        // Wait K(kt) (+Q on kt=0); leaves V(kt) in flight
        CP_WAIT(1);
        __syncthreads();

        if (kt < L) { issue_k(kt + 1, slot ^ 1); CP_COMMIT(); }

        float* Ksb = Ks + slot * FA_BC * K_ST;

        // S = Q @ K^T  (warp tile 32x16)
        float sacc[2][2][4];
        #pragma unroll
        for (int i = 0; i < 2; i++)
            #pragma unroll
            for (int j = 0; j < 2; j++)
                #pragma unroll
                for (int r = 0; r < 4; r++) sacc[i][j][r] = 0.f;

        #pragma unroll
        for (int ks = 0; ks < D_; ks += 8) {
            float afr[2][4], bfr[2][2];
            #pragma unroll
            for (int mi = 0; mi < 2; mi++) {
                int rb = wy * 32 + mi * 16;
                afr[mi][0] = Qs[(rb + t4) * Q_ST + ks + tm4];
                afr[mi][1] = Qs[(rb + 8 + t4) * Q_ST + ks + tm4];
                afr[mi][2] = Qs[(rb + t4) * Q_ST + ks + tm4 + 4];
                afr[mi][3] = Qs[(rb + 8 + t4) * Q_ST + ks + tm4 + 4];
            }
            #pragma unroll
            for (int ni = 0; ni < 2; ni++) {
                int cb = wx * 16 + ni * 8;
                bfr[ni][0] = Ksb[(cb + t4) * K_ST + ks + tm4];
                bfr[ni][1] = Ksb[(cb + t4) * K_ST + ks + tm4 + 4];
            }
            #pragma unroll
            for (int mi = 0; mi < 2; mi++)
                #pragma unroll
                for (int ni = 0; ni < 2; ni++)
                    mma_tf32(sacc[mi][ni], afr[mi], bfr[ni]);
        }

        // Scale + causal mask + store S. col offset vs rows: coff = k0 - q0
        const bool diag = (kt >= 2 * qt);
        const int coff = kt * FA_BC - q0;
        #pragma unroll
        for (int mi = 0; mi < 2; mi++) {
            #pragma unroll
            for (int ni = 0; ni < 2; ni++) {
                int rA = wy * 32 + mi * 16 + t4;
                int cA = wx * 16 + ni * 8 + tm4 * 2;
                #pragma unroll
                for (int half = 0; half < 2; half++) {
                    int r = rA + half * 8;
                    float v0 = sacc[mi][ni][half * 2 + 0] * SCALE_;
                    float v1 = sacc[mi][ni][half * 2 + 1] * SCALE_;
                    if (diag) {
                        if (coff + cA > r) v0 = -INFINITY;
                        if (coff + cA + 1 > r) v1 = -INFINITY;
                    }
                    *(float2*)(&Ss[r * S_ST + cA]) = make_float2(v0, v1);
                }
            }
        }

        // Wait V(kt) (leave K(kt+1) in flight; on last iter wait all)
        if (kt < L) CP_WAIT(1); else CP_WAIT(0);
        __syncthreads();

        // Online softmax: 4 threads per row, 16 cols each
        {
            const int srow = tid >> 2;
            const int ssub = tid & 3;
            float* Srow = Ss + srow * S_ST + ssub * 16;
            float mo = m_s[srow];
            float mx = mo;
            #pragma unroll
            for (int j = 0; j < 16; j++) mx = fmaxf(mx, Srow[j]);
            mx = fmaxf(mx, __shfl_xor_sync(0xffffffffu, mx, 1));
            mx = fmaxf(mx, __shfl_xor_sync(0xffffffffu, mx, 2));
            float sum = 0.f;
            #pragma unroll
            for (int j = 0; j < 16; j++) {
                float p = __expf(Srow[j] - mx);
                Srow[j] = tf32r(p);
                sum += p;
            }
            sum += __shfl_xor_sync(0xffffffffu, sum, 1);
            sum += __shfl_xor_sync(0xffffffffu, sum, 2);
            if (ssub == 0) {
                float alpha = __expf(mo - mx);
                a_s[srow] = alpha;
                l_s[srow] = l_s[srow] * alpha + sum;
                m_s[srow] = mx;
            }
        }
        __syncthreads();

        // Rescale + PV (warp tile 32x32)
        #pragma unroll
        for (int mi = 0; mi < 2; mi++) {
            int rb = wy * 32 + mi * 16 + t4;
            float al0 = a_s[rb];
            float al1 = a_s[rb + 8];
            #pragma unroll
            for (int ni = 0; ni < 4; ni++) {
                o[mi][ni][0] *= al0; o[mi][ni][1] *= al0;
                o[mi][ni][2] *= al1; o[mi][ni][3] *= al1;
            }
        }

        #pragma unroll
        for (int ks = 0; ks < FA_BC; ks += 8) {
            float afr[2][4], bfr[4][2];
            #pragma unroll
            for (int mi = 0; mi < 2; mi++) {
                int rb = wy * 32 + mi * 16;
                afr[mi][0] = Ss[(rb + t4) * S_ST + ks + tm4];
                afr[mi][1] = Ss[(rb + 8 + t4) * S_ST + ks + tm4];
                afr[mi][2] = Ss[(rb + t4) * S_ST + ks + tm4 + 4];
                afr[mi][3] = Ss[(rb + 8 + t4) * S_ST + ks + tm4 + 4];
            }
            #pragma unroll
            for (int ni = 0; ni < 4; ni++) {
                int cb = wx * 32 + ni * 8;
                bfr[ni][0] = Vs[(ks + tm4) * V_ST + cb + t4];
                bfr[ni][1] = Vs[(ks + tm4 + 4) * V_ST + cb + t4];
            }
            #pragma unroll
            for (int mi = 0; mi < 2; mi++)
                #pragma unroll
                for (int ni = 0; ni < 4; ni++)
                    mma_tf32(o[mi][ni], afr[mi], bfr[ni]);
        }
        __syncthreads();   // all PV reads of V done before refill

        if (kt < L) { issue_v(kt + 1); CP_COMMIT(); }
    }

    // Epilogue: divide by l, write y (tf32-rounded for gemm_out)
    float* ybase = y + (size_t)b * T_ * C_ + h * D_;
    #pragma unroll
    for (int mi = 0; mi < 2; mi++) {
        int rb = wy * 32 + mi * 16 + t4;
        float inv0 = 1.f / l_s[rb];
        float inv1 = 1.f / l_s[rb + 8];
        #pragma unroll
        for (int ni = 0; ni < 4; ni++) {
            int col = wx * 32 + ni * 8 + tm4 * 2;
            float* d0 = ybase + (size_t)(q0 + rb) * C_ + col;
            float* d1 = ybase + (size_t)(q0 + rb + 8) * C_ + col;
            *(float2*)d0 = make_float2(tf32r(o[mi][ni][0] * inv0), tf32r(o[mi][ni][1] * inv0));
            *(float2*)d1 = make_float2(tf32r(o[mi][ni][2] * inv1), tf32r(o[mi][ni][3] * inv1));
        }
    }
}

// ---------------------------------------------------------------------------
// Launch
// ---------------------------------------------------------------------------
extern "C" void kernel_launch(void* const* d_in, const int* in_sizes, int n_in,
                              void* d_out, int out_size)
{
    const float* x   = (const float*)d_in[0];
    const float* cs  = (const float*)d_in[1];
    const float* sn  = (const float*)d_in[2];
    const float* Wq  = (const float*)d_in[3];
    const float* Wk  = (const float*)d_in[4];
    const float* Wv  = (const float*)d_in[5];
    const float* Wo  = (const float*)d_in[6];
    float* out = (float*)d_out;

    float *qp, *kp, *vp, *yp, *xp, *wqp, *wkp, *wvp, *wop;
    cudaGetSymbolAddress((void**)&qp, g_q);
    cudaGetSymbolAddress((void**)&kp, g_k);
    cudaGetSymbolAddress((void**)&vp, g_v);
    cudaGetSymbolAddress((void**)&yp, g_y);
    cudaGetSymbolAddress((void**)&xp, g_x);
    cudaGetSymbolAddress((void**)&wqp, g_wq);
    cudaGetSymbolAddress((void**)&wkp, g_wk);
    cudaGetSymbolAddress((void**)&wvp, g_wv);
    cudaGetSymbolAddress((void**)&wop, g_wo);

    const int gemm_smem = GEMM_SM_FLOATS * 4;   // 107520 B
    cudaFuncSetAttribute(gemm_qkv, cudaFuncAttributeMaxDynamicSharedMemorySize, gemm_smem);
    cudaFuncSetAttribute(gemm_out, cudaFuncAttributeMaxDynamicSharedMemorySize, gemm_smem);
    const int fa_smem = FA_SMEM_FLOATS * 4;     // 206336 B
    cudaFuncSetAttribute(flash_attn_tf32, cudaFuncAttributeMaxDynamicSharedMemorySize, fa_smem);

    dim3 blk256(256), blk512(512);
    // Pre-round inputs to tf32
    {
        int n4;
        n4 = (M_ * C_) / 4;
        tf32_round_kernel<<<(n4 + 255) / 256, blk256>>>((const float4*)x, (float4*)xp, n4);
        n4 = (C_ * C_) / 4;
        tf32_round_kernel<<<(n4 + 255) / 256, blk256>>>((const float4*)Wq, (float4*)wqp, n4);
        n4 = (C_ * KVC_) / 4;
        tf32_round_kernel<<<(n4 + 255) / 256, blk256>>>((const float4*)Wk, (float4*)wkp, n4);
        tf32_round_kernel<<<(n4 + 255) / 256, blk256>>>((const float4*)Wv, (float4*)wvp, n4);
        n4 = (C_ * C_) / 4;
        tf32_round_kernel<<<(n4 + 255) / 256, blk256>>>((const float4*)Wo, (float4*)wop, n4);
    }
    // Fused Q/K/V projections + RoPE + RMSNorm
    gemm_qkv<<<dim3(24, M_ / 128), blk256, gemm_smem>>>(xp, wqp, wkp, wvp, cs, sn, qp, kp, vp);
    // Attention (Br=128, 512 threads)
    flash_attn_tf32<<<dim3(T_ / FA_BR, B_ * H_), blk512, fa_smem>>>(qp, kp, vp, yp);
    // Output projection
    gemm_out<<<dim3(C_ / 128, M_ / 128), blk256, gemm_smem>>>(yp, wop, out);
}

// round 14
// speedup vs baseline: 1.0473x; 1.0473x over previous
#include <cuda_runtime.h>
#include <cuda_bf16.h>
#include <math.h>
#include <stdint.h>

// Problem constants
#define B_ 2
#define T_ 2048
#define C_ 2048
#define H_ 16
#define KVH_ 4
#define D_ 128
#define M_ (B_ * T_)          // 4096
#define KVC_ (KVH_ * D_)      // 512
#define SCALE_ 0.08838834764831845f
#define RMS_EPS 1.1920929e-07f

// ---------------------------------------------------------------------------
// Scratch (device globals; no allocation allowed)
// ---------------------------------------------------------------------------
__device__ float g_q[(size_t)M_ * C_];
__device__ float g_k[(size_t)M_ * KVC_];
__device__ float g_v[(size_t)M_ * KVC_];
__device__ float g_y[(size_t)M_ * C_];
__device__ float g_x[(size_t)M_ * C_];
__device__ float g_wq[(size_t)C_ * C_];    // transposed [n][k]
__device__ float g_wk[(size_t)C_ * KVC_];  // transposed [n][k]
__device__ float g_wv[(size_t)C_ * KVC_];  // transposed [n][k]
__device__ float g_wo[(size_t)C_ * C_];    // transposed [n][k]

// ---------------------------------------------------------------------------
// helpers
// ---------------------------------------------------------------------------
__device__ __forceinline__ uint32_t smem_u32(const void* p) {
    uint32_t a;
    asm("{ .reg .u64 t; cvta.to.shared.u64 t, %1; cvt.u32.u64 %0, t; }" : "=r"(a) : "l"(p));
    return a;
}

__device__ __forceinline__ float tf32r(float x) {
    unsigned u;
    asm("cvt.rna.tf32.f32 %0, %1;" : "=r"(u) : "f"(x));
    return __uint_as_float(u);
}

__device__ __forceinline__ void cp16(uint32_t s, const void* g) {
    asm volatile("cp.async.cg.shared.global [%0], [%1], 16;" :: "r"(s), "l"(g) : "memory");
}
#define CP_COMMIT() asm volatile("cp.async.commit_group;" ::: "memory")
#define CP_WAIT(n)  asm volatile("cp.async.wait_group %0;" :: "n"(n) : "memory")

__device__ __forceinline__ void mma_tf32(float* c, const float* a, const float* b) {
    const unsigned* A = reinterpret_cast<const unsigned*>(a);
    const unsigned* Bv = reinterpret_cast<const unsigned*>(b);
    asm volatile(
        "mma.sync.aligned.m16n8k8.row.col.f32.tf32.tf32.f32 "
        "{%0,%1,%2,%3}, {%4,%5,%6,%7}, {%8,%9}, {%0,%1,%2,%3};\n"
        : "+f"(c[0]), "+f"(c[1]), "+f"(c[2]), "+f"(c[3])
        : "r"(A[0]), "r"(A[1]), "r"(A[2]), "r"(A[3]), "r"(Bv[0]), "r"(Bv[1]));
}

// ldmatrix x4: four 8x8 b16 tiles == four 8x4 tf32 tiles.
// Thread i of tile j receives the 32-bit word at (row i/4, tf32-col i%4).
__device__ __forceinline__ void ldsm4(uint32_t* r, uint32_t addr) {
    asm volatile("ldmatrix.sync.aligned.m8n8.x4.shared.b16 {%0,%1,%2,%3}, [%4];"
        : "=r"(r[0]), "=r"(r[1]), "=r"(r[2]), "=r"(r[3]) : "r"(addr));
}

// ---------------------------------------------------------------------------
// tf32 pre-round kernel (elementwise, for x)
// ---------------------------------------------------------------------------
__global__ __launch_bounds__(256) void tf32_round_kernel(
    const float4* __restrict__ src, float4* __restrict__ dst, int n4)
{
    int i = blockIdx.x * 256 + threadIdx.x;
    if (i < n4) {
        float4 v = src[i];
        dst[i] = make_float4(tf32r(v.x), tf32r(v.y), tf32r(v.z), tf32r(v.w));
    }
}

// tf32 round + transpose: dst[n][k] = tf32(src[k][n]). 32x32 tiles, 256 thr.
__global__ __launch_bounds__(256) void tf32_round_T_kernel(
    const float* __restrict__ src, float* __restrict__ dst, int K, int N)
{
    __shared__ float t[32][33];
    const int n0 = blockIdx.x * 32;
    const int k0 = blockIdx.y * 32;
    const int tx = threadIdx.x & 31;
    const int ty = threadIdx.x >> 5;     // 0..7
    #pragma unroll
    for (int i = 0; i < 32; i += 8)
        t[ty + i][tx] = src[(size_t)(k0 + ty + i) * N + n0 + tx];
    __syncthreads();
    #pragma unroll
    for (int i = 0; i < 32; i += 8)
        dst[(size_t)(n0 + ty + i) * K + k0 + tx] = tf32r(t[tx][ty + i]);
}

// ---------------------------------------------------------------------------
// cp.async 3-stage pipelined tf32 GEMM mainloop with ldmatrix fragment loads.
// Tile 128x128, K-step 32, 256 threads (8 warps 2x4), warp tile 64x32.
// A [m][k] K-major; Bt [n][k] K-major (pre-transposed weights).
// Both smem tiles 128 rows x 32 floats, padded stride 36 (banks 4r+c).
// ---------------------------------------------------------------------------
#define A_ST 36
#define TBUF (128 * A_ST)                       // 4608 floats
#define STAGES 3
#define GEMM_SM_FLOATS (STAGES * 2 * TBUF)      // 27648 floats = 110592 B
#define STAGE_ST 132

__device__ __forceinline__ void gemm_main(
    const float* __restrict__ Ab, const float* __restrict__ Bt,
    int K, float* sm, float acc[4][4][4])
{
    const uint32_t sA = smem_u32(sm);
    const uint32_t sB = sA + (uint32_t)STAGES * TBUF * 4;

    const int tid = threadIdx.x;
    const int lane = tid & 31;
    const int wid = tid >> 5;
    const int wy = wid & 1;
    const int wx = wid >> 1;

    #pragma unroll
    for (int i = 0; i < 4; i++)
        #pragma unroll
        for (int j = 0; j < 4; j++)
            #pragma unroll
            for (int r = 0; r < 4; r++) acc[i][j][r] = 0.f;

    const int NT = K >> 5;

    // ldmatrix per-lane offsets (floats):
    // A tiles: t0=(r+0..7,ks) t1=(r+8..15,ks) t2=(r+0..7,ks+4) t3=(r+8..15,ks+4)
    const int laneA = ((lane & 8) + (lane & 7)) * A_ST + (lane >> 4) * 4;
    // B tiles: t0=(n+0..7,ks) t1=(n+0..7,ks+4) t2=(n+8..15,ks) t3=(n+8..15,ks+4)
    const int laneB = (((lane >> 4) << 3) + (lane & 7)) * A_ST + ((lane >> 3) & 1) * 4;

    auto load_stage = [&](int t, int slot) {
        const float* An = Ab + t * 32;
        const float* Bn = Bt + t * 32;
        #pragma unroll
        for (int i = 0; i < 4; i++) {
            int idx = tid + i * 256;
            int r = idx >> 3, cg = (idx & 7) << 2;
            cp16(sA + (uint32_t)(slot * TBUF + r * A_ST + cg) * 4,
                 An + (size_t)r * K + cg);
        }
        #pragma unroll
        for (int i = 0; i < 4; i++) {
            int idx = tid + i * 256;
            int r = idx >> 3, cg = (idx & 7) << 2;
            cp16(sB + (uint32_t)(slot * TBUF + r * A_ST + cg) * 4,
                 Bn + (size_t)r * K + cg);
        }
    };

    #pragma unroll
    for (int s = 0; s < STAGES - 1; s++) {
        if (s < NT) load_stage(s, s);
        CP_COMMIT();
    }

    int slot = 0;
    for (int t = 0; t < NT; t++) {
        CP_WAIT(STAGES - 2);
        __syncthreads();

        int u = t + STAGES - 1;
        int uslot = slot + STAGES - 1;
        if (uslot >= STAGES) uslot -= STAGES;
        if (u < NT) load_stage(u, uslot);
        CP_COMMIT();

        const uint32_t aS = sA + (uint32_t)(slot * TBUF) * 4;
        const uint32_t bS = sB + (uint32_t)(slot * TBUF) * 4;
        #pragma unroll
        for (int ks = 0; ks < 32; ks += 8) {
            uint32_t af[4][4], bf[2][4];
            #pragma unroll
            for (int mi = 0; mi < 4; mi++)
                ldsm4(af[mi], aS + (uint32_t)((wy * 64 + mi * 16) * A_ST + ks + laneA) * 4);
            #pragma unroll
            for (int p = 0; p < 2; p++)
                ldsm4(bf[p], bS + (uint32_t)((wx * 32 + p * 16) * A_ST + ks + laneB) * 4);
            #pragma unroll
            for (int mi = 0; mi < 4; mi++)
                #pragma unroll
                for (int ni = 0; ni < 4; ni++)
                    mma_tf32(acc[mi][ni], (float*)af[mi],
                             (float*)(&bf[ni >> 1][(ni & 1) * 2]));
        }
        if (++slot == STAGES) slot = 0;
    }
}

// Plain epilogue
template <bool ROUND>
__device__ __forceinline__ void epi_plain(float acc[4][4][4], float* out, int Nout)
{
    const int tid = threadIdx.x;
    const int lane = tid & 31;
    const int wid = tid >> 5;
    const int t4 = lane >> 2;
    const int tm4 = lane & 3;
    const int wy = wid & 1;
    const int wx = wid >> 1;
    #pragma unroll
    for (int mi = 0; mi < 4; mi++) {
        int row = wy * 64 + mi * 16 + t4;
        #pragma unroll
        for (int ni = 0; ni < 4; ni++) {
            int col = wx * 32 + ni * 8 + tm4 * 2;
            float a0 = acc[mi][ni][0], a1 = acc[mi][ni][1];
            float a2 = acc[mi][ni][2], a3 = acc[mi][ni][3];
            if (ROUND) { a0 = tf32r(a0); a1 = tf32r(a1); a2 = tf32r(a2); a3 = tf32r(a3); }
            *(float2*)(out + (size_t)row * Nout + col) = make_float2(a0, a1);
            *(float2*)(out + (size_t)(row + 8) * Nout + col) = make_float2(a2, a3);
        }
    }
}

// RoPE + RMSNorm epilogue (stores tf32-rounded)
__device__ __forceinline__ void epi_rope(
    float acc[4][4][4], float* sm,
    const float* __restrict__ cs, const float* __restrict__ sn,
    float* out, int Nout, int m0)
{
    float* stage = sm;
    const int tid = threadIdx.x;
    const int lane = tid & 31;
    const int wid = tid >> 5;
    const int t4 = lane >> 2;
    const int tm4 = lane & 3;
    const int wy = wid & 1;
    const int wx = wid >> 1;

    __syncthreads();
    #pragma unroll
    for (int mi = 0; mi < 4; mi++) {
        int row = wy * 64 + mi * 16 + t4;
        #pragma unroll
        for (int ni = 0; ni < 4; ni++) {
            int col = wx * 32 + ni * 8 + tm4 * 2;
            *(float2*)(&stage[row * STAGE_ST + col]) = make_float2(acc[mi][ni][0], acc[mi][ni][1]);
            *(float2*)(&stage[(row + 8) * STAGE_ST + col]) = make_float2(acc[mi][ni][2], acc[mi][ni][3]);
        }
    }
    __syncthreads();

    {
        const int r = tid >> 1;
        const int hf = tid & 1;
        const int tpos = (m0 + r) & (T_ - 1);
        const float* cr = cs + tpos * 64;
        const float* sr = sn + tpos * 64;
        float* row = &stage[r * STAGE_ST];

        float ss = 0.f;
        #pragma unroll 8
        for (int j = 0; j < 64; j++) {
            float x1 = row[j], x2 = row[j + 64];
            float c = cr[j], s = sr[j];
            float val = hf ? (x2 * c - x1 * s) : (x1 * c + x2 * s);
            ss += val * val;
        }
        ss += __shfl_xor_sync(0xffffffffu, ss, 1);
        float inv = rsqrtf(ss * (1.f / 128.f) + RMS_EPS);

        #pragma unroll 8
        for (int j = 0; j < 64; j++) {
            float x1 = row[j], x2 = row[j + 64];
            float c = cr[j], s = sr[j];
            float val = hf ? (x2 * c - x1 * s) : (x1 * c + x2 * s);
            row[hf * 64 + j] = tf32r(val * inv);
        }
    }
    __syncthreads();

    {
        const int c4 = lane * 4;
        const int rb = tid >> 5;
        #pragma unroll
        for (int p = 0; p < 16; p++) {
            int row = p * 8 + rb;
            float4 v = *(const float4*)(&stage[row * STAGE_ST + c4]);
            *(float4*)(out + (size_t)row * Nout + c4) = v;
        }
    }
}

// ---------------------------------------------------------------------------
// Fused QKV projection + RoPE + RMSNorm. grid (24, 32), 256 threads, 2 CTA/SM.
// Weights pre-transposed to [n][k], row stride C_.
// ---------------------------------------------------------------------------
__global__ __launch_bounds__(256, 2) void gemm_qkv(
    const float* __restrict__ x,
    const float* __restrict__ WqT, const float* __restrict__ WkT, const float* __restrict__ WvT,
    const float* __restrict__ cs, const float* __restrict__ sn,
    float* __restrict__ q, float* __restrict__ k, float* __restrict__ v)
{
    extern __shared__ float sm[];
    const int bx = blockIdx.x;
    const int m0 = blockIdx.y * 128;

    const float* Bt;
    float* outp;
    int Nb, colt;
    bool dorope;
    if (bx < 16)      { Bt = WqT; outp = q; Nb = C_;   colt = bx * 128;        dorope = true; }
    else if (bx < 20) { Bt = WkT; outp = k; Nb = KVC_; colt = (bx - 16) * 128; dorope = true; }
    else              { Bt = WvT; outp = v; Nb = KVC_; colt = (bx - 20) * 128; dorope = false; }

    float acc[4][4][4];
    gemm_main(x + (size_t)m0 * C_, Bt + (size_t)colt * C_, C_, sm, acc);

    float* out_tile = outp + (size_t)m0 * Nb + colt;
    if (dorope) epi_rope(acc, sm, cs, sn, out_tile, Nb, m0);
    else        epi_plain<true>(acc, out_tile, Nb);
}

// ---------------------------------------------------------------------------
// Output projection: out = y @ Wo (WoT pre-transposed). grid (16, 32).
// ---------------------------------------------------------------------------
__global__ __launch_bounds__(256, 2) void gemm_out(
    const float* __restrict__ y, const float* __restrict__ WoT, float* __restrict__ out)
{
    extern __shared__ float sm[];
    const int m0 = blockIdx.y * 128;
    const int colt = blockIdx.x * 128;
    float acc[4][4][4];
    gemm_main(y + (size_t)m0 * C_, WoT + (size_t)colt * C_, C_, sm, acc);
    epi_plain<false>(acc, out + (size_t)m0 * C_ + colt, C_);
}

// ---------------------------------------------------------------------------
// Flash attention (causal, GQA rep=4), tf32 mma, cp.async double-buffered K/V.
// 256 threads (8 warps 2x4). Identical to R11 (best-known attention).
// ---------------------------------------------------------------------------
#define FA_BR 64
#define FA_BC 64
#define Q_ST 132
#define K_ST 132
#define V_ST 136
#define S_ST 68

#define SM_Q   0
#define SM_K   (FA_BR * Q_ST)
#define SM_V   (SM_K + 2 * FA_BC * K_ST)
#define SM_S   (SM_V + 2 * FA_BC * V_ST)
#define SM_M   (SM_S + FA_BR * S_ST)
#define SM_L   (SM_M + FA_BR)
#define SM_A   (SM_L + FA_BR)
#define FA_SMEM_FLOATS (SM_A + FA_BR)     // 189184 B

__global__ __launch_bounds__(256, 1) void flash_attn_tf32(
    const float* __restrict__ q, const float* __restrict__ k,
    const float* __restrict__ v, float* __restrict__ y)
{
    extern __shared__ float sm[];
    float* Qs = sm + SM_Q;
    float* Ks = sm + SM_K;
    float* Vs = sm + SM_V;
    float* Ss = sm + SM_S;
    float* m_s = sm + SM_M;
    float* l_s = sm + SM_L;
    float* a_s = sm + SM_A;
    const uint32_t sbase = smem_u32(sm);

    const int tid = threadIdx.x;
    const int lane = tid & 31;
    const int wid = tid >> 5;
    const int t4 = lane >> 2;
    const int tm4 = lane & 3;
    const int wy = wid & 1;
    const int wx = wid >> 1;

    const int bh = blockIdx.y;
    const int b = bh >> 4;
    const int h = bh & 15;
    const int kvh = h >> 2;
    const int qt = gridDim.x - 1 - blockIdx.x;
    const int q0 = qt * FA_BR;

    const float* qbase = q + (size_t)b * T_ * C_ + h * D_;
    const float* kbase = k + (size_t)b * T_ * KVC_ + kvh * D_;
    const float* vbase = v + (size_t)b * T_ * KVC_ + kvh * D_;

    auto issue_kv = [&](int kt, int slot) {
        const float* kb = kbase + (size_t)(kt * FA_BC) * KVC_;
        const float* vb = vbase + (size_t)(kt * FA_BC) * KVC_;
        #pragma unroll
        for (int i = 0; i < 8; i++) {
            int idx = tid + i * 256;
            int r = idx >> 5;
            int c = (idx & 31) << 2;
            cp16(sbase + (uint32_t)(SM_K + slot * FA_BC * K_ST + r * K_ST + c) * 4,
                 kb + (size_t)r * KVC_ + c);
            cp16(sbase + (uint32_t)(SM_V + slot * FA_BC * V_ST + r * V_ST + c) * 4,
                 vb + (size_t)r * KVC_ + c);
        }
    };

    #pragma unroll
    for (int i = 0; i < 8; i++) {
        int idx = tid + i * 256;
        int r = idx >> 5;
        int c = (idx & 31) << 2;
        cp16(sbase + (uint32_t)(SM_Q + r * Q_ST + c) * 4,
             qbase + (size_t)(q0 + r) * C_ + c);
    }
    issue_kv(0, 0);
    CP_COMMIT();

    if (tid < FA_BR) { m_s[tid] = -INFINITY; l_s[tid] = 0.f; }

    float o[2][4][4];
    #pragma unroll
    for (int i = 0; i < 2; i++)
        #pragma unroll
        for (int j = 0; j < 4; j++)
            #pragma unroll
            for (int r = 0; r < 4; r++) o[i][j][r] = 0.f;

    for (int kt = 0; kt <= qt; kt++) {
        const int slot = kt & 1;
        CP_WAIT(0);
        __syncthreads();

        if (kt < qt) { issue_kv(kt + 1, slot ^ 1); CP_COMMIT(); }

        float* Ksb = Ks + slot * FA_BC * K_ST;
        float* Vsb = Vs + slot * FA_BC * V_ST;

        float sacc[2][2][4];
        #pragma unroll
        for (int i = 0; i < 2; i++)
            #pragma unroll
            for (int j = 0; j < 2; j++)
                #pragma unroll
                for (int r = 0; r < 4; r++) sacc[i][j][r] = 0.f;

        #pragma unroll
        for (int ks = 0; ks < D_; ks += 8) {
            float afr[2][4], bfr[2][2];
            #pragma unroll
            for (int mi = 0; mi < 2; mi++) {
                int rb = wy * 32 + mi * 16;
                afr[mi][0] = Qs[(rb + t4) * Q_ST + ks + tm4];
                afr[mi][1] = Qs[(rb + 8 + t4) * Q_ST + ks + tm4];
                afr[mi][2] = Qs[(rb + t4) * Q_ST + ks + tm4 + 4];
                afr[mi][3] = Qs[(rb + 8 + t4) * Q_ST + ks + tm4 + 4];
            }
            #pragma unroll
            for (int ni = 0; ni < 2; ni++) {
                int cb = wx * 16 + ni * 8;
                bfr[ni][0] = Ksb[(cb + t4) * K_ST + ks + tm4];
                bfr[ni][1] = Ksb[(cb + t4) * K_ST + ks + tm4 + 4];
            }
            #pragma unroll
            for (int mi = 0; mi < 2; mi++)
                #pragma unroll
                for (int ni = 0; ni < 2; ni++)
                    mma_tf32(sacc[mi][ni], afr[mi], bfr[ni]);
        }

        const bool diag = (kt == qt);
        #pragma unroll
        for (int mi = 0; mi < 2; mi++) {
            #pragma unroll
            for (int ni = 0; ni < 2; ni++) {
                int rA = wy * 32 + mi * 16 + t4;
                int cA = wx * 16 + ni * 8 + tm4 * 2;
                #pragma unroll
                for (int half = 0; half < 2; half++) {
                    int r = rA + half * 8;
                    float v0 = sacc[mi][ni][half * 2 + 0] * SCALE_;
                    float v1 = sacc[mi][ni][half * 2 + 1] * SCALE_;
                    if (diag) {
                        if (cA > r) v0 = -INFINITY;
                        if (cA + 1 > r) v1 = -INFINITY;
                    }
                    *(float2*)(&Ss[r * S_ST + cA]) = make_float2(v0, v1);
                }
            }
        }
        __syncthreads();

        {
            const int srow = tid >> 2;
            const int ssub = tid & 3;
            float* Srow = Ss + srow * S_ST + ssub * 16;
            float mo = m_s[srow];
            float mx = mo;
            #pragma unroll
            for (int j = 0; j < 16; j++) mx = fmaxf(mx, Srow[j]);
            mx = fmaxf(mx, __shfl_xor_sync(0xffffffffu, mx, 1));
            mx = fmaxf(mx, __shfl_xor_sync(0xffffffffu, mx, 2));
            float sum = 0.f;
            #pragma unroll
            for (int j = 0; j < 16; j++) {
                float p = __expf(Srow[j] - mx);
                Srow[j] = tf32r(p);
                sum += p;
            }
            sum += __shfl_xor_sync(0xffffffffu, sum, 1);
            sum += __shfl_xor_sync(0xffffffffu, sum, 2);
            if (ssub == 0) {
                float alpha = __expf(mo - mx);
                a_s[srow] = alpha;
                l_s[srow] = l_s[srow] * alpha + sum;
                m_s[srow] = mx;
            }
        }
        __syncthreads();

        #pragma unroll
        for (int mi = 0; mi < 2; mi++) {
            int rb = wy * 32 + mi * 16 + t4;
            float al0 = a_s[rb];
            float al1 = a_s[rb + 8];
            #pragma unroll
            for (int ni = 0; ni < 4; ni++) {
                o[mi][ni][0] *= al0; o[mi][ni][1] *= al0;
                o[mi][ni][2] *= al1; o[mi][ni][3] *= al1;
            }
        }

        #pragma unroll
        for (int ks = 0; ks < FA_BC; ks += 8) {
            float afr[2][4], bfr[4][2];
            #pragma unroll
            for (int mi = 0; mi < 2; mi++) {
                int rb = wy * 32 + mi * 16;
                afr[mi][0] = Ss[(rb + t4) * S_ST + ks + tm4];
                afr[mi][1] = Ss[(rb + 8 + t4) * S_ST + ks + tm4];
                afr[mi][2] = Ss[(rb + t4) * S_ST + ks + tm4 + 4];
                afr[mi][3] = Ss[(rb + 8 + t4) * S_ST + ks + tm4 + 4];
            }
            #pragma unroll
            for (int ni = 0; ni < 4; ni++) {
                int cb = wx * 32 + ni * 8;
                bfr[ni][0] = Vsb[(ks + tm4) * V_ST + cb + t4];
                bfr[ni][1] = Vsb[(ks + tm4 + 4) * V_ST + cb + t4];
            }
            #pragma unroll
            for (int mi = 0; mi < 2; mi++)
                #pragma unroll
                for (int ni = 0; ni < 4; ni++)
                    mma_tf32(o[mi][ni], afr[mi], bfr[ni]);
        }
    }

    __syncthreads();
    float* ybase = y + (size_t)b * T_ * C_ + h * D_;
    #pragma unroll
    for (int mi = 0; mi < 2; mi++) {
        int rb = wy * 32 + mi * 16 + t4;
        float inv0 = 1.f / l_s[rb];
        float inv1 = 1.f / l_s[rb + 8];
        #pragma unroll
        for (int ni = 0; ni < 4; ni++) {
            int col = wx * 32 + ni * 8 + tm4 * 2;
            float* d0 = ybase + (size_t)(q0 + rb) * C_ + col;
            float* d1 = ybase + (size_t)(q0 + rb + 8) * C_ + col;
            *(float2*)d0 = make_float2(tf32r(o[mi][ni][0] * inv0), tf32r(o[mi][ni][1] * inv0));
            *(float2*)d1 = make_float2(tf32r(o[mi][ni][2] * inv1), tf32r(o[mi][ni][3] * inv1));
        }
    }
}

// ---------------------------------------------------------------------------
// Launch
// ---------------------------------------------------------------------------
extern "C" void kernel_launch(void* const* d_in, const int* in_sizes, int n_in,
                              void* d_out, int out_size)
{
    const float* x   = (const float*)d_in[0];
    const float* cs  = (const float*)d_in[1];
    const float* sn  = (const float*)d_in[2];
    const float* Wq  = (const float*)d_in[3];
    const float* Wk  = (const float*)d_in[4];
    const float* Wv  = (const float*)d_in[5];
    const float* Wo  = (const float*)d_in[6];
    float* out = (float*)d_out;

    float *qp, *kp, *vp, *yp, *xp, *wqp, *wkp, *wvp, *wop;
    cudaGetSymbolAddress((void**)&qp, g_q);
    cudaGetSymbolAddress((void**)&kp, g_k);
    cudaGetSymbolAddress((void**)&vp, g_v);
    cudaGetSymbolAddress((void**)&yp, g_y);
    cudaGetSymbolAddress((void**)&xp, g_x);
    cudaGetSymbolAddress((void**)&wqp, g_wq);
    cudaGetSymbolAddress((void**)&wkp, g_wk);
    cudaGetSymbolAddress((void**)&wvp, g_wv);
    cudaGetSymbolAddress((void**)&wop, g_wo);

    const int gemm_smem = GEMM_SM_FLOATS * 4;   // 110592 B -> 2 CTA/SM
    cudaFuncSetAttribute(gemm_qkv, cudaFuncAttributeMaxDynamicSharedMemorySize, gemm_smem);
    cudaFuncSetAttribute(gemm_out, cudaFuncAttributeMaxDynamicSharedMemorySize, gemm_smem);
    const int fa_smem = FA_SMEM_FLOATS * 4;     // 189184 B
    cudaFuncSetAttribute(flash_attn_tf32, cudaFuncAttributeMaxDynamicSharedMemorySize, fa_smem);

    dim3 blk256(256);
    // Pre-round x (elementwise); pre-round + transpose weights to [n][k]
    {
        int n4 = (M_ * C_) / 4;
        tf32_round_kernel<<<(n4 + 255) / 256, blk256>>>((const float4*)x, (float4*)xp, n4);
        tf32_round_T_kernel<<<dim3(C_ / 32, C_ / 32), blk256>>>(Wq, wqp, C_, C_);
        tf32_round_T_kernel<<<dim3(KVC_ / 32, C_ / 32), blk256>>>(Wk, wkp, C_, KVC_);
        tf32_round_T_kernel<<<dim3(KVC_ / 32, C_ / 32), blk256>>>(Wv, wvp, C_, KVC_);
        tf32_round_T_kernel<<<dim3(C_ / 32, C_ / 32), blk256>>>(Wo, wop, C_, C_);
    }
    // Fused Q/K/V projections + RoPE + RMSNorm
    gemm_qkv<<<dim3(24, M_ / 128), blk256, gemm_smem>>>(xp, wqp, wkp, wvp, cs, sn, qp, kp, vp);
    // Attention
    flash_attn_tf32<<<dim3(T_ / FA_BR, B_ * H_), blk256, fa_smem>>>(qp, kp, vp, yp);
    // Output projection
    gemm_out<<<dim3(C_ / 128, M_ / 128), blk256, gemm_smem>>>(yp, wop, out);
}

// round 15
// speedup vs baseline: 1.0652x; 1.0172x over previous
#include <cuda_runtime.h>
#include <cuda_bf16.h>
#include <math.h>
#include <stdint.h>

// Problem constants
#define B_ 2
#define T_ 2048
#define C_ 2048
#define H_ 16
#define KVH_ 4
#define D_ 128
#define M_ (B_ * T_)          // 4096
#define KVC_ (KVH_ * D_)      // 512
#define SCALE_ 0.08838834764831845f
#define RMS_EPS 1.1920929e-07f

// ---------------------------------------------------------------------------
// Scratch (device globals; no allocation allowed)
// ---------------------------------------------------------------------------
__device__ float g_q[(size_t)M_ * C_];
__device__ float g_k[(size_t)M_ * KVC_];
__device__ float g_v[(size_t)M_ * KVC_];
__device__ float g_y[(size_t)M_ * C_];
__device__ float g_x[(size_t)M_ * C_];
__device__ float g_wq[(size_t)C_ * C_];    // transposed [n][k]
__device__ float g_wk[(size_t)C_ * KVC_];  // transposed [n][k]
__device__ float g_wv[(size_t)C_ * KVC_];  // transposed [n][k]
__device__ float g_wo[(size_t)C_ * C_];    // transposed [n][k]

// ---------------------------------------------------------------------------
// helpers
// ---------------------------------------------------------------------------
__device__ __forceinline__ uint32_t smem_u32(const void* p) {
    uint32_t a;
    asm("{ .reg .u64 t; cvta.to.shared.u64 t, %1; cvt.u32.u64 %0, t; }" : "=r"(a) : "l"(p));
    return a;
}

__device__ __forceinline__ float tf32r(float x) {
    unsigned u;
    asm("cvt.rna.tf32.f32 %0, %1;" : "=r"(u) : "f"(x));
    return __uint_as_float(u);
}

__device__ __forceinline__ void cp16(uint32_t s, const void* g) {
    asm volatile("cp.async.cg.shared.global [%0], [%1], 16;" :: "r"(s), "l"(g) : "memory");
}
#define CP_COMMIT() asm volatile("cp.async.commit_group;" ::: "memory")
#define CP_WAIT(n)  asm volatile("cp.async.wait_group %0;" :: "n"(n) : "memory")

__device__ __forceinline__ void mma_tf32(float* c, const float* a, const float* b) {
    const unsigned* A = reinterpret_cast<const unsigned*>(a);
    const unsigned* Bv = reinterpret_cast<const unsigned*>(b);
    asm volatile(
        "mma.sync.aligned.m16n8k8.row.col.f32.tf32.tf32.f32 "
        "{%0,%1,%2,%3}, {%4,%5,%6,%7}, {%8,%9}, {%0,%1,%2,%3};\n"
        : "+f"(c[0]), "+f"(c[1]), "+f"(c[2]), "+f"(c[3])
        : "r"(A[0]), "r"(A[1]), "r"(A[2]), "r"(A[3]), "r"(Bv[0]), "r"(Bv[1]));
}

// ldmatrix x4: four 8x8 b16 tiles == four 8x4 tf32 tiles.
__device__ __forceinline__ void ldsm4(uint32_t* r, uint32_t addr) {
    asm volatile("ldmatrix.sync.aligned.m8n8.x4.shared.b16 {%0,%1,%2,%3}, [%4];"
        : "=r"(r[0]), "=r"(r[1]), "=r"(r[2]), "=r"(r[3]) : "r"(addr));
}

// ---------------------------------------------------------------------------
// tf32 pre-round kernel (elementwise, for x)
// ---------------------------------------------------------------------------
__global__ __launch_bounds__(256) void tf32_round_kernel(
    const float4* __restrict__ src, float4* __restrict__ dst, int n4)
{
    int i = blockIdx.x * 256 + threadIdx.x;
    if (i < n4) {
        float4 v = src[i];
        dst[i] = make_float4(tf32r(v.x), tf32r(v.y), tf32r(v.z), tf32r(v.w));
    }
}

// tf32 round + transpose: dst[n][k] = tf32(src[k][n]). 32x32 tiles, 256 thr.
__global__ __launch_bounds__(256) void tf32_round_T_kernel(
    const float* __restrict__ src, float* __restrict__ dst, int K, int N)
{
    __shared__ float t[32][33];
    const int n0 = blockIdx.x * 32;
    const int k0 = blockIdx.y * 32;
    const int tx = threadIdx.x & 31;
    const int ty = threadIdx.x >> 5;     // 0..7
    #pragma unroll
    for (int i = 0; i < 32; i += 8)
        t[ty + i][tx] = src[(size_t)(k0 + ty + i) * N + n0 + tx];
    __syncthreads();
    #pragma unroll
    for (int i = 0; i < 32; i += 8)
        dst[(size_t)(n0 + ty + i) * K + k0 + tx] = tf32r(t[tx][ty + i]);
}

// ---------------------------------------------------------------------------
// cp.async 3-stage pipelined tf32 GEMM mainloop with ldmatrix fragment loads.
// (unchanged from R14)
// ---------------------------------------------------------------------------
#define A_ST 36
#define TBUF (128 * A_ST)
#define STAGES 3
#define GEMM_SM_FLOATS (STAGES * 2 * TBUF)      // 110592 B
#define STAGE_ST 132

__device__ __forceinline__ void gemm_main(
    const float* __restrict__ Ab, const float* __restrict__ Bt,
    int K, float* sm, float acc[4][4][4])
{
    const uint32_t sA = smem_u32(sm);
    const uint32_t sB = sA + (uint32_t)STAGES * TBUF * 4;

    const int tid = threadIdx.x;
    const int lane = tid & 31;
    const int wid = tid >> 5;
    const int wy = wid & 1;
    const int wx = wid >> 1;

    #pragma unroll
    for (int i = 0; i < 4; i++)
        #pragma unroll
        for (int j = 0; j < 4; j++)
            #pragma unroll
            for (int r = 0; r < 4; r++) acc[i][j][r] = 0.f;

    const int NT = K >> 5;

    const int laneA = ((lane & 8) + (lane & 7)) * A_ST + (lane >> 4) * 4;
    const int laneB = (((lane >> 4) << 3) + (lane & 7)) * A_ST + ((lane >> 3) & 1) * 4;

    auto load_stage = [&](int t, int slot) {
        const float* An = Ab + t * 32;
        const float* Bn = Bt + t * 32;
        #pragma unroll
        for (int i = 0; i < 4; i++) {
            int idx = tid + i * 256;
            int r = idx >> 3, cg = (idx & 7) << 2;
            cp16(sA + (uint32_t)(slot * TBUF + r * A_ST + cg) * 4,
                 An + (size_t)r * K + cg);
        }
        #pragma unroll
        for (int i = 0; i < 4; i++) {
            int idx = tid + i * 256;
            int r = idx >> 3, cg = (idx & 7) << 2;
            cp16(sB + (uint32_t)(slot * TBUF + r * A_ST + cg) * 4,
                 Bn + (size_t)r * K + cg);
        }
    };

    #pragma unroll
    for (int s = 0; s < STAGES - 1; s++) {
        if (s < NT) load_stage(s, s);
        CP_COMMIT();
    }

    int slot = 0;
    for (int t = 0; t < NT; t++) {
        CP_WAIT(STAGES - 2);
        __syncthreads();

        int u = t + STAGES - 1;
        int uslot = slot + STAGES - 1;
        if (uslot >= STAGES) uslot -= STAGES;
        if (u < NT) load_stage(u, uslot);
        CP_COMMIT();

        const uint32_t aS = sA + (uint32_t)(slot * TBUF) * 4;
        const uint32_t bS = sB + (uint32_t)(slot * TBUF) * 4;
        #pragma unroll
        for (int ks = 0; ks < 32; ks += 8) {
            uint32_t af[4][4], bf[2][4];
            #pragma unroll
            for (int mi = 0; mi < 4; mi++)
                ldsm4(af[mi], aS + (uint32_t)((wy * 64 + mi * 16) * A_ST + ks + laneA) * 4);
            #pragma unroll
            for (int p = 0; p < 2; p++)
                ldsm4(bf[p], bS + (uint32_t)((wx * 32 + p * 16) * A_ST + ks + laneB) * 4);
            #pragma unroll
            for (int mi = 0; mi < 4; mi++)
                #pragma unroll
                for (int ni = 0; ni < 4; ni++)
                    mma_tf32(acc[mi][ni], (float*)af[mi],
                             (float*)(&bf[ni >> 1][(ni & 1) * 2]));
        }
        if (++slot == STAGES) slot = 0;
    }
}

// Plain epilogue
template <bool ROUND>
__device__ __forceinline__ void epi_plain(float acc[4][4][4], float* out, int Nout)
{
    const int tid = threadIdx.x;
    const int lane = tid & 31;
    const int wid = tid >> 5;
    const int t4 = lane >> 2;
    const int tm4 = lane & 3;
    const int wy = wid & 1;
    const int wx = wid >> 1;
    #pragma unroll
    for (int mi = 0; mi < 4; mi++) {
        int row = wy * 64 + mi * 16 + t4;
        #pragma unroll
        for (int ni = 0; ni < 4; ni++) {
            int col = wx * 32 + ni * 8 + tm4 * 2;
            float a0 = acc[mi][ni][0], a1 = acc[mi][ni][1];
            float a2 = acc[mi][ni][2], a3 = acc[mi][ni][3];
            if (ROUND) { a0 = tf32r(a0); a1 = tf32r(a1); a2 = tf32r(a2); a3 = tf32r(a3); }
            *(float2*)(out + (size_t)row * Nout + col) = make_float2(a0, a1);
            *(float2*)(out + (size_t)(row + 8) * Nout + col) = make_float2(a2, a3);
        }
    }
}

// RoPE + RMSNorm epilogue (stores tf32-rounded)
__device__ __forceinline__ void epi_rope(
    float acc[4][4][4], float* sm,
    const float* __restrict__ cs, const float* __restrict__ sn,
    float* out, int Nout, int m0)
{
    float* stage = sm;
    const int tid = threadIdx.x;
    const int lane = tid & 31;
    const int wid = tid >> 5;
    const int t4 = lane >> 2;
    const int tm4 = lane & 3;
    const int wy = wid & 1;
    const int wx = wid >> 1;

    __syncthreads();
    #pragma unroll
    for (int mi = 0; mi < 4; mi++) {
        int row = wy * 64 + mi * 16 + t4;
        #pragma unroll
        for (int ni = 0; ni < 4; ni++) {
            int col = wx * 32 + ni * 8 + tm4 * 2;
            *(float2*)(&stage[row * STAGE_ST + col]) = make_float2(acc[mi][ni][0], acc[mi][ni][1]);
            *(float2*)(&stage[(row + 8) * STAGE_ST + col]) = make_float2(acc[mi][ni][2], acc[mi][ni][3]);
        }
    }
    __syncthreads();

    {
        const int r = tid >> 1;
        const int hf = tid & 1;
        const int tpos = (m0 + r) & (T_ - 1);
        const float* cr = cs + tpos * 64;
        const float* sr = sn + tpos * 64;
        float* row = &stage[r * STAGE_ST];

        float ss = 0.f;
        #pragma unroll 8
        for (int j = 0; j < 64; j++) {
            float x1 = row[j], x2 = row[j + 64];
            float c = cr[j], s = sr[j];
            float val = hf ? (x2 * c - x1 * s) : (x1 * c + x2 * s);
            ss += val * val;
        }
        ss += __shfl_xor_sync(0xffffffffu, ss, 1);
        float inv = rsqrtf(ss * (1.f / 128.f) + RMS_EPS);

        #pragma unroll 8
        for (int j = 0; j < 64; j++) {
            float x1 = row[j], x2 = row[j + 64];
            float c = cr[j], s = sr[j];
            float val = hf ? (x2 * c - x1 * s) : (x1 * c + x2 * s);
            row[hf * 64 + j] = tf32r(val * inv);
        }
    }
    __syncthreads();

    {
        const int c4 = lane * 4;
        const int rb = tid >> 5;
        #pragma unroll
        for (int p = 0; p < 16; p++) {
            int row = p * 8 + rb;
            float4 v = *(const float4*)(&stage[row * STAGE_ST + c4]);
            *(float4*)(out + (size_t)row * Nout + c4) = v;
        }
    }
}

// ---------------------------------------------------------------------------
// Fused QKV projection + RoPE + RMSNorm. grid (24, 32), 256 threads, 2 CTA/SM.
// ---------------------------------------------------------------------------
__global__ __launch_bounds__(256, 2) void gemm_qkv(
    const float* __restrict__ x,
    const float* __restrict__ WqT, const float* __restrict__ WkT, const float* __restrict__ WvT,
    const float* __restrict__ cs, const float* __restrict__ sn,
    float* __restrict__ q, float* __restrict__ k, float* __restrict__ v)
{
    extern __shared__ float sm[];
    const int bx = blockIdx.x;
    const int m0 = blockIdx.y * 128;

    const float* Bt;
    float* outp;
    int Nb, colt;
    bool dorope;
    if (bx < 16)      { Bt = WqT; outp = q; Nb = C_;   colt = bx * 128;        dorope = true; }
    else if (bx < 20) { Bt = WkT; outp = k; Nb = KVC_; colt = (bx - 16) * 128; dorope = true; }
    else              { Bt = WvT; outp = v; Nb = KVC_; colt = (bx - 20) * 128; dorope = false; }

    float acc[4][4][4];
    gemm_main(x + (size_t)m0 * C_, Bt + (size_t)colt * C_, C_, sm, acc);

    float* out_tile = outp + (size_t)m0 * Nb + colt;
    if (dorope) epi_rope(acc, sm, cs, sn, out_tile, Nb, m0);
    else        epi_plain<true>(acc, out_tile, Nb);
}

// ---------------------------------------------------------------------------
// Output projection: out = y @ Wo (WoT pre-transposed). grid (16, 32).
// ---------------------------------------------------------------------------
__global__ __launch_bounds__(256, 2) void gemm_out(
    const float* __restrict__ y, const float* __restrict__ WoT, float* __restrict__ out)
{
    extern __shared__ float sm[];
    const int m0 = blockIdx.y * 128;
    const int colt = blockIdx.x * 128;
    float acc[4][4][4];
    gemm_main(y + (size_t)m0 * C_, WoT + (size_t)colt * C_, C_, sm, acc);
    epi_plain<false>(acc, out + (size_t)m0 * C_ + colt, C_);
}

// ---------------------------------------------------------------------------
// Flash attention (causal, GQA rep=4), tf32 mma + ldmatrix fragment loads.
// 256 threads (8 warps 2x4), Br=Bc=64, cp.async double-buffered K/V.
// Q/K/S fragments via ldmatrix (layouts are K-major; strides mod 32 = 4,
// conflict-free). V B-fragments stay scalar LDS (N-major).
// ---------------------------------------------------------------------------
#define FA_BR 64
#define FA_BC 64
#define Q_ST 132
#define K_ST 132
#define V_ST 136
#define S_ST 68

#define SM_Q   0
#define SM_K   (FA_BR * Q_ST)
#define SM_V   (SM_K + 2 * FA_BC * K_ST)
#define SM_S   (SM_V + 2 * FA_BC * V_ST)
#define SM_M   (SM_S + FA_BR * S_ST)
#define SM_L   (SM_M + FA_BR)
#define SM_A   (SM_L + FA_BR)
#define FA_SMEM_FLOATS (SM_A + FA_BR)     // 189184 B

__global__ __launch_bounds__(256, 1) void flash_attn_tf32(
    const float* __restrict__ q, const float* __restrict__ k,
    const float* __restrict__ v, float* __restrict__ y)
{
    extern __shared__ float sm[];
    float* Qs = sm + SM_Q;
    float* Vs = sm + SM_V;
    float* Ss = sm + SM_S;
    float* m_s = sm + SM_M;
    float* l_s = sm + SM_L;
    float* a_s = sm + SM_A;
    const uint32_t sbase = smem_u32(sm);

    const int tid = threadIdx.x;
    const int lane = tid & 31;
    const int wid = tid >> 5;
    const int t4 = lane >> 2;
    const int tm4 = lane & 3;
    const int wy = wid & 1;
    const int wx = wid >> 1;

    const int bh = blockIdx.y;
    const int b = bh >> 4;
    const int h = bh & 15;
    const int kvh = h >> 2;
    const int qt = gridDim.x - 1 - blockIdx.x;
    const int q0 = qt * FA_BR;

    const float* qbase = q + (size_t)b * T_ * C_ + h * D_;
    const float* kbase = k + (size_t)b * T_ * KVC_ + kvh * D_;
    const float* vbase = v + (size_t)b * T_ * KVC_ + kvh * D_;

    // ldmatrix lane offsets (floats), per stride
    const int lrow = (lane & 8) + (lane & 7);          // A-tile row pattern
    const int lcol = (lane >> 4) * 4;                  // A-tile col half
    const int laneA_Q = lrow * Q_ST + lcol;
    const int laneA_S = lrow * S_ST + lcol;
    const int brow = ((lane >> 4) << 3) + (lane & 7);  // B-tile row pattern
    const int bcol = ((lane >> 3) & 1) * 4;            // B-tile col half
    const int laneB_K = brow * K_ST + bcol;

    auto issue_kv = [&](int kt, int slot) {
        const float* kb = kbase + (size_t)(kt * FA_BC) * KVC_;
        const float* vb = vbase + (size_t)(kt * FA_BC) * KVC_;
        #pragma unroll
        for (int i = 0; i < 8; i++) {
            int idx = tid + i * 256;
            int r = idx >> 5;
            int c = (idx & 31) << 2;
            cp16(sbase + (uint32_t)(SM_K + slot * FA_BC * K_ST + r * K_ST + c) * 4,
                 kb + (size_t)r * KVC_ + c);
            cp16(sbase + (uint32_t)(SM_V + slot * FA_BC * V_ST + r * V_ST + c) * 4,
                 vb + (size_t)r * KVC_ + c);
        }
    };

    #pragma unroll
    for (int i = 0; i < 8; i++) {
        int idx = tid + i * 256;
        int r = idx >> 5;
        int c = (idx & 31) << 2;
        cp16(sbase + (uint32_t)(SM_Q + r * Q_ST + c) * 4,
             qbase + (size_t)(q0 + r) * C_ + c);
    }
    issue_kv(0, 0);
    CP_COMMIT();

    if (tid < FA_BR) { m_s[tid] = -INFINITY; l_s[tid] = 0.f; }

    float o[2][4][4];
    #pragma unroll
    for (int i = 0; i < 2; i++)
        #pragma unroll
        for (int j = 0; j < 4; j++)
            #pragma unroll
            for (int r = 0; r < 4; r++) o[i][j][r] = 0.f;

    for (int kt = 0; kt <= qt; kt++) {
        const int slot = kt & 1;
        CP_WAIT(0);
        __syncthreads();

        if (kt < qt) { issue_kv(kt + 1, slot ^ 1); CP_COMMIT(); }

        const uint32_t qS = sbase + (uint32_t)SM_Q * 4;
        const uint32_t kS = sbase + (uint32_t)(SM_K + slot * FA_BC * K_ST) * 4;
        float* Vsb = Vs + slot * FA_BC * V_ST;

        // S = Q @ K^T  (warp tile 32x16), ldmatrix loads
        float sacc[2][2][4];
        #pragma unroll
        for (int i = 0; i < 2; i++)
            #pragma unroll
            for (int j = 0; j < 2; j++)
                #pragma unroll
                for (int r = 0; r < 4; r++) sacc[i][j][r] = 0.f;

        #pragma unroll
        for (int ks = 0; ks < D_; ks += 8) {
            uint32_t af[2][4], bf[4];
            #pragma unroll
            for (int mi = 0; mi < 2; mi++)
                ldsm4(af[mi], qS + (uint32_t)((wy * 32 + mi * 16) * Q_ST + ks + laneA_Q) * 4);
            ldsm4(bf, kS + (uint32_t)((wx * 16) * K_ST + ks + laneB_K) * 4);
            #pragma unroll
            for (int mi = 0; mi < 2; mi++)
                #pragma unroll
                for (int ni = 0; ni < 2; ni++)
                    mma_tf32(sacc[mi][ni], (float*)af[mi], (float*)(&bf[ni * 2]));
        }

        const bool diag = (kt == qt);
        #pragma unroll
        for (int mi = 0; mi < 2; mi++) {
            #pragma unroll
            for (int ni = 0; ni < 2; ni++) {
                int rA = wy * 32 + mi * 16 + t4;
                int cA = wx * 16 + ni * 8 + tm4 * 2;
                #pragma unroll
                for (int half = 0; half < 2; half++) {
                    int r = rA + half * 8;
                    float v0 = sacc[mi][ni][half * 2 + 0] * SCALE_;
                    float v1 = sacc[mi][ni][half * 2 + 1] * SCALE_;
                    if (diag) {
                        if (cA > r) v0 = -INFINITY;
                        if (cA + 1 > r) v1 = -INFINITY;
                    }
                    *(float2*)(&Ss[r * S_ST + cA]) = make_float2(v0, v1);
                }
            }
        }
        __syncthreads();

        {
            const int srow = tid >> 2;
            const int ssub = tid & 3;
            float* Srow = Ss + srow * S_ST + ssub * 16;
            float mo = m_s[srow];
            float mx = mo;
            #pragma unroll
            for (int j = 0; j < 16; j++) mx = fmaxf(mx, Srow[j]);
            mx = fmaxf(mx, __shfl_xor_sync(0xffffffffu, mx, 1));
            mx = fmaxf(mx, __shfl_xor_sync(0xffffffffu, mx, 2));
            float sum = 0.f;
            #pragma unroll
            for (int j = 0; j < 16; j++) {
                float p = __expf(Srow[j] - mx);
                Srow[j] = tf32r(p);
                sum += p;
            }
            sum += __shfl_xor_sync(0xffffffffu, sum, 1);
            sum += __shfl_xor_sync(0xffffffffu, sum, 2);
            if (ssub == 0) {
                float alpha = __expf(mo - mx);
                a_s[srow] = alpha;
                l_s[srow] = l_s[srow] * alpha + sum;
                m_s[srow] = mx;
            }
        }
        __syncthreads();

        #pragma unroll
        for (int mi = 0; mi < 2; mi++) {
            int rb = wy * 32 + mi * 16 + t4;
            float al0 = a_s[rb];
            float al1 = a_s[rb + 8];
            #pragma unroll
            for (int ni = 0; ni < 4; ni++) {
                o[mi][ni][0] *= al0; o[mi][ni][1] *= al0;
                o[mi][ni][2] *= al1; o[mi][ni][3] *= al1;
            }
        }

        // O += P @ V: P via ldmatrix, V via scalar LDS (N-major)
        const uint32_t sS = sbase + (uint32_t)SM_S * 4;
        #pragma unroll
        for (int ks = 0; ks < FA_BC; ks += 8) {
            uint32_t af[2][4];
            float bfr[4][2];
            #pragma unroll
            for (int mi = 0; mi < 2; mi++)
                ldsm4(af[mi], sS + (uint32_t)((wy * 32 + mi * 16) * S_ST + ks + laneA_S) * 4);
            #pragma unroll
            for (int ni = 0; ni < 4; ni++) {
                int cb = wx * 32 + ni * 8;
                bfr[ni][0] = Vsb[(ks + tm4) * V_ST + cb + t4];
                bfr[ni][1] = Vsb[(ks + tm4 + 4) * V_ST + cb + t4];
            }
            #pragma unroll
            for (int mi = 0; mi < 2; mi++)
                #pragma unroll
                for (int ni = 0; ni < 4; ni++)
                    mma_tf32(o[mi][ni], (float*)af[mi], bfr[ni]);
        }
    }

    __syncthreads();
    float* ybase = y + (size_t)b * T_ * C_ + h * D_;
    #pragma unroll
    for (int mi = 0; mi < 2; mi++) {
        int rb = wy * 32 + mi * 16 + t4;
        float inv0 = 1.f / l_s[rb];
        float inv1 = 1.f / l_s[rb + 8];
        #pragma unroll
        for (int ni = 0; ni < 4; ni++) {
            int col = wx * 32 + ni * 8 + tm4 * 2;
            float* d0 = ybase + (size_t)(q0 + rb) * C_ + col;
            float* d1 = ybase + (size_t)(q0 + rb + 8) * C_ + col;
            *(float2*)d0 = make_float2(tf32r(o[mi][ni][0] * inv0), tf32r(o[mi][ni][1] * inv0));
            *(float2*)d1 = make_float2(tf32r(o[mi][ni][2] * inv1), tf32r(o[mi][ni][3] * inv1));
        }
    }
}

// ---------------------------------------------------------------------------
// Launch
// ---------------------------------------------------------------------------
extern "C" void kernel_launch(void* const* d_in, const int* in_sizes, int n_in,
                              void* d_out, int out_size)
{
    const float* x   = (const float*)d_in[0];
    const float* cs  = (const float*)d_in[1];
    const float* sn  = (const float*)d_in[2];
    const float* Wq  = (const float*)d_in[3];
    const float* Wk  = (const float*)d_in[4];
    const float* Wv  = (const float*)d_in[5];
    const float* Wo  = (const float*)d_in[6];
    float* out = (float*)d_out;

    float *qp, *kp, *vp, *yp, *xp, *wqp, *wkp, *wvp, *wop;
    cudaGetSymbolAddress((void**)&qp, g_q);
    cudaGetSymbolAddress((void**)&kp, g_k);
    cudaGetSymbolAddress((void**)&vp, g_v);
    cudaGetSymbolAddress((void**)&yp, g_y);
    cudaGetSymbolAddress((void**)&xp, g_x);
    cudaGetSymbolAddress((void**)&wqp, g_wq);
    cudaGetSymbolAddress((void**)&wkp, g_wk);
    cudaGetSymbolAddress((void**)&wvp, g_wv);
    cudaGetSymbolAddress((void**)&wop, g_wo);

    const int gemm_smem = GEMM_SM_FLOATS * 4;   // 110592 B -> 2 CTA/SM
    cudaFuncSetAttribute(gemm_qkv, cudaFuncAttributeMaxDynamicSharedMemorySize, gemm_smem);
    cudaFuncSetAttribute(gemm_out, cudaFuncAttributeMaxDynamicSharedMemorySize, gemm_smem);
    const int fa_smem = FA_SMEM_FLOATS * 4;     // 189184 B
    cudaFuncSetAttribute(flash_attn_tf32, cudaFuncAttributeMaxDynamicSharedMemorySize, fa_smem);

    dim3 blk256(256);
    {
        int n4 = (M_ * C_) / 4;
        tf32_round_kernel<<<(n4 + 255) / 256, blk256>>>((const float4*)x, (float4*)xp, n4);
        tf32_round_T_kernel<<<dim3(C_ / 32, C_ / 32), blk256>>>(Wq, wqp, C_, C_);
        tf32_round_T_kernel<<<dim3(KVC_ / 32, C_ / 32), blk256>>>(Wk, wkp, C_, KVC_);
        tf32_round_T_kernel<<<dim3(KVC_ / 32, C_ / 32), blk256>>>(Wv, wvp, C_, KVC_);
        tf32_round_T_kernel<<<dim3(C_ / 32, C_ / 32), blk256>>>(Wo, wop, C_, C_);
    }
    gemm_qkv<<<dim3(24, M_ / 128), blk256, gemm_smem>>>(xp, wqp, wkp, wvp, cs, sn, qp, kp, vp);
    flash_attn_tf32<<<dim3(T_ / FA_BR, B_ * H_), blk256, fa_smem>>>(qp, kp, vp, yp);
    gemm_out<<<dim3(C_ / 128, M_ / 128), blk256, gemm_smem>>>(yp, wop, out);
}